// round 1
// baseline (speedup 1.0000x reference)
#include <cuda_runtime.h>
#include <float.h>

#define NOFF 44
#define HD   64
#define SEQ  8192
#define HNUM 16
#define BNUM 2
#define TPB  128

__constant__ int c_off[NOFF] = {
    0,1,2,3,4,5,6,7,8,9,10,11,12,13,14,15,16,
    17,18,19,20,21,22,23,24,25,26,27,28,29,30,31,32,
    48,64,96,128,192,256,384,512,768,1024,1536
};

// dot of 64-float q (in 16 float4 regs) with a 16-float4 row pointer
__device__ __forceinline__ float dot64(const float4* qr, const float4* __restrict__ p) {
    float s0 = 0.f, s1 = 0.f, s2 = 0.f, s3 = 0.f;
    #pragma unroll
    for (int j = 0; j < 16; j += 4) {
        float4 x0 = p[j + 0];
        float4 x1 = p[j + 1];
        float4 x2 = p[j + 2];
        float4 x3 = p[j + 3];
        s0 = fmaf(qr[j + 0].x, x0.x, fmaf(qr[j + 0].y, x0.y, fmaf(qr[j + 0].z, x0.z, fmaf(qr[j + 0].w, x0.w, s0))));
        s1 = fmaf(qr[j + 1].x, x1.x, fmaf(qr[j + 1].y, x1.y, fmaf(qr[j + 1].z, x1.z, fmaf(qr[j + 1].w, x1.w, s1))));
        s2 = fmaf(qr[j + 2].x, x2.x, fmaf(qr[j + 2].y, x2.y, fmaf(qr[j + 2].z, x2.z, fmaf(qr[j + 2].w, x2.w, s2))));
        s3 = fmaf(qr[j + 3].x, x3.x, fmaf(qr[j + 3].y, x3.y, fmaf(qr[j + 3].z, x3.z, fmaf(qr[j + 3].w, x3.w, s3))));
    }
    return (s0 + s1) + (s2 + s3);
}

__global__ __launch_bounds__(TPB)
void dsqg_attn_kernel(const float* __restrict__ q,
                      const float* __restrict__ k,
                      const float* __restrict__ v,
                      const float* __restrict__ pb,
                      const float* __restrict__ se,
                      const float* __restrict__ ph,
                      float* __restrict__ out) {
    const int n = blockIdx.x * TPB + threadIdx.x;
    const int h = blockIdx.y;
    const int b = blockIdx.z;

    __shared__ float s_se[NOFF * HD];
    __shared__ float s_pb[NOFF];
    __shared__ float s_cos[NOFF];
    __shared__ float s_sin[NOFF];

    for (int i = threadIdx.x; i < NOFF * HD; i += TPB) s_se[i] = se[i];
    if (threadIdx.x < NOFF) {
        s_pb[threadIdx.x] = pb[threadIdx.x * HNUM + h];
        float p = ph[threadIdx.x * HNUM + h];
        s_cos[threadIdx.x] = cosf(p);
        s_sin[threadIdx.x] = sinf(p);
    }
    __syncthreads();

    const size_t bh   = ((size_t)b * HNUM + h) * SEQ;
    const float4* qp  = (const float4*)(q + (bh + (size_t)n) * HD);
    const float4* kb  = (const float4*)(k + bh * HD);
    const float4* vb  = (const float4*)(v + bh * HD);

    // ---- load q into registers ----
    float4 qr[16];
    #pragma unroll
    for (int j = 0; j < 16; j++) qr[j] = qp[j];

    const float sc = 0.125f;  // 1/sqrt(64)

    // ---- pass 1: scores ----
    float s[NOFF];
    for (int i = 0; i < NOFF; i++) {
        const int d = c_off[i];
        if (d > n) { s[i] = -FLT_MAX * 0.5f; continue; }
        const float4* krow = kb + (size_t)(n - d) * 16;
        float qk   = dot64(qr, krow);
        float qdyn = dot64(qr, (const float4*)(s_se + i * HD));
        s[i] = fmaf(qk + qdyn, sc, s_pb[i]);
    }

    // ---- softmax over 44 offsets ----
    float m = -FLT_MAX;
    #pragma unroll
    for (int i = 0; i < NOFF; i++) m = fmaxf(m, s[i]);
    float sum = 0.f;
    #pragma unroll
    for (int i = 0; i < NOFF; i++) {
        float e = __expf(s[i] - m);
        s[i] = e;
        sum += e;
    }
    const float inv = 1.0f / sum;

    // ---- pass 2: rotated-V accumulation ----
    float2 o[32];
    #pragma unroll
    for (int j = 0; j < 32; j++) { o[j].x = 0.f; o[j].y = 0.f; }

    for (int i = 0; i < NOFF; i++) {
        const int d = c_off[i];
        if (d > n) continue;
        const float w  = s[i] * inv;
        const float pc = w * s_cos[i];
        const float ps = w * s_sin[i];
        const float4* vrow = vb + (size_t)(n - d) * 16;
        #pragma unroll
        for (int j = 0; j < 16; j++) {
            float4 vv = vrow[j];
            // pair 2j: (vv.x, vv.y)
            o[2 * j].x     = fmaf(vv.x, pc, fmaf(-vv.y, ps, o[2 * j].x));
            o[2 * j].y     = fmaf(vv.x, ps, fmaf( vv.y, pc, o[2 * j].y));
            // pair 2j+1: (vv.z, vv.w)
            o[2 * j + 1].x = fmaf(vv.z, pc, fmaf(-vv.w, ps, o[2 * j + 1].x));
            o[2 * j + 1].y = fmaf(vv.z, ps, fmaf( vv.w, pc, o[2 * j + 1].y));
        }
    }

    // ---- store ----
    float4* op = (float4*)(out + (bh + (size_t)n) * HD);
    #pragma unroll
    for (int j = 0; j < 16; j++) {
        float4 r;
        r.x = o[2 * j].x;
        r.y = o[2 * j].y;
        r.z = o[2 * j + 1].x;
        r.w = o[2 * j + 1].y;
        op[j] = r;
    }
}

extern "C" void kernel_launch(void* const* d_in, const int* in_sizes, int n_in,
                              void* d_out, int out_size) {
    const float* q  = (const float*)d_in[0];
    const float* k  = (const float*)d_in[1];
    const float* v  = (const float*)d_in[2];
    const float* pb = (const float*)d_in[3];
    const float* se = (const float*)d_in[4];
    const float* ph = (const float*)d_in[5];
    float* out = (float*)d_out;

    dim3 grid(SEQ / TPB, HNUM, BNUM);
    dsqg_attn_kernel<<<grid, TPB>>>(q, k, v, pb, se, ph, out);
}

// round 2
// speedup vs baseline: 1.1309x; 1.1309x over previous
#include <cuda_runtime.h>
#include <float.h>

#define NOFF 44
#define HD   64
#define SEQ  8192
#define HNUM 16
#define BNUM 2
#define TPB  256
#define WPB  (TPB / 32)   // 8 queries per block

__constant__ int c_off[NOFF] = {
    0,1,2,3,4,5,6,7,8,9,10,11,12,13,14,15,16,
    17,18,19,20,21,22,23,24,25,26,27,28,29,30,31,32,
    48,64,96,128,192,256,384,512,768,1024,1536
};

__global__ __launch_bounds__(TPB)
void dsqg_attn_kernel(const float* __restrict__ q,
                      const float* __restrict__ k,
                      const float* __restrict__ v,
                      const float* __restrict__ pb,
                      const float* __restrict__ se,
                      const float* __restrict__ ph,
                      float* __restrict__ out) {
    const int lane = threadIdx.x & 31;
    const int wid  = threadIdx.x >> 5;
    const int n    = blockIdx.x * WPB + wid;   // query index
    const int h    = blockIdx.y;
    const int b    = blockIdx.z;

    __shared__ float2 s_se[NOFF * 32];   // se rows as float2 (lane t -> dims 2t,2t+1)
    __shared__ float  s_pb[NOFF];
    __shared__ float  s_cos[NOFF];
    __shared__ float  s_sin[NOFF];

    for (int i = threadIdx.x; i < NOFF * 32; i += TPB)
        s_se[i] = ((const float2*)se)[i];
    if (threadIdx.x < NOFF) {
        s_pb[threadIdx.x] = pb[threadIdx.x * HNUM + h];
        float p = ph[threadIdx.x * HNUM + h];
        s_cos[threadIdx.x] = cosf(p);
        s_sin[threadIdx.x] = sinf(p);
    }
    __syncthreads();

    const size_t bh = ((size_t)b * HNUM + h) * SEQ;
    const float2* kb = (const float2*)(k + bh * HD);
    const float2* vb = (const float2*)(v + bh * HD);

    // each lane owns head dims (2*lane, 2*lane+1)
    const float2 qv = ((const float2*)(q + (bh + (size_t)n) * HD))[lane];
    const float sc = 0.125f;  // 1/sqrt(64)

    // ---- pass 1: scores (qk + qdyn fused: q·(k+se)) ----
    float s[NOFF];
    #pragma unroll
    for (int i = 0; i < NOFF; i++) {
        const int d = c_off[i];
        if (d <= n) {
            float2 kv  = kb[(size_t)(n - d) * 32 + lane];
            float2 sev = s_se[i * 32 + lane];
            float part = fmaf(qv.x, kv.x + sev.x, qv.y * (kv.y + sev.y));
            #pragma unroll
            for (int off = 16; off > 0; off >>= 1)
                part += __shfl_xor_sync(0xffffffffu, part, off);
            s[i] = fmaf(part, sc, s_pb[i]);
        } else {
            s[i] = -1e30f;
        }
    }

    // ---- softmax over 44 offsets (identical on all lanes) ----
    float m = -FLT_MAX;
    #pragma unroll
    for (int i = 0; i < NOFF; i++) m = fmaxf(m, s[i]);
    float sum = 0.f;
    #pragma unroll
    for (int i = 0; i < NOFF; i++) {
        float e = __expf(s[i] - m);
        s[i] = e;
        sum += e;
    }
    const float inv = 1.0f / sum;

    // ---- pass 2: rotated-V accumulation (lane's float2 = rotation pair) ----
    float2 o = make_float2(0.f, 0.f);
    #pragma unroll
    for (int i = 0; i < NOFF; i++) {
        const int d = c_off[i];
        if (d > n) continue;
        const float w  = s[i] * inv;
        const float pc = w * s_cos[i];
        const float ps = w * s_sin[i];
        float2 vv = vb[(size_t)(n - d) * 32 + lane];
        o.x = fmaf(vv.x, pc, fmaf(-vv.y, ps, o.x));
        o.y = fmaf(vv.x, ps, fmaf( vv.y, pc, o.y));
    }

    ((float2*)(out + (bh + (size_t)n) * HD))[lane] = o;
}

extern "C" void kernel_launch(void* const* d_in, const int* in_sizes, int n_in,
                              void* d_out, int out_size) {
    const float* q  = (const float*)d_in[0];
    const float* k  = (const float*)d_in[1];
    const float* v  = (const float*)d_in[2];
    const float* pb = (const float*)d_in[3];
    const float* se = (const float*)d_in[4];
    const float* ph = (const float*)d_in[5];
    float* out = (float*)d_out;

    dim3 grid(SEQ / WPB, HNUM, BNUM);
    dsqg_attn_kernel<<<grid, TPB>>>(q, k, v, pb, se, ph, out);
}

// round 3
// speedup vs baseline: 1.3009x; 1.1503x over previous
#include <cuda_runtime.h>
#include <float.h>

#define NOFF 44
#define HD   64
#define SEQ  8192
#define HNUM 16
#define BNUM 2
#define TPB  256
#define QPW  4                   // queries per warp
#define QPB  (TPB / 32 * QPW)    // 32 queries per block

__constant__ int c_off[NOFF] = {
    0,1,2,3,4,5,6,7,8,9,10,11,12,13,14,15,16,
    17,18,19,20,21,22,23,24,25,26,27,28,29,30,31,32,
    48,64,96,128,192,256,384,512,768,1024,1536
};

__global__ __launch_bounds__(TPB)
void dsqg_attn_kernel(const float* __restrict__ q,
                      const float* __restrict__ k,
                      const float* __restrict__ v,
                      const float* __restrict__ pb,
                      const float* __restrict__ se,
                      const float* __restrict__ ph,
                      float* __restrict__ out) {
    const int lane = threadIdx.x & 31;
    const int wid  = threadIdx.x >> 5;
    const int sub  = lane >> 3;      // which query in warp (0..3)
    const int ln8  = lane & 7;       // dim-octet index (owns dims 8*ln8 .. 8*ln8+7)
    const int n    = blockIdx.x * QPB + wid * QPW + sub;   // query index
    const int h    = blockIdx.y;
    const int b    = blockIdx.z;

    __shared__ float4 s_se[NOFF * 16];   // se rows as float4
    __shared__ float  s_pb[NOFF];
    __shared__ float  s_cos[NOFF];
    __shared__ float  s_sin[NOFF];

    for (int i = threadIdx.x; i < NOFF * 16; i += TPB)
        s_se[i] = ((const float4*)se)[i];
    if (threadIdx.x < NOFF) {
        s_pb[threadIdx.x] = pb[threadIdx.x * HNUM + h];
        float p = ph[threadIdx.x * HNUM + h];
        s_cos[threadIdx.x] = cosf(p);
        s_sin[threadIdx.x] = sinf(p);
    }
    __syncthreads();

    const size_t bh = ((size_t)b * HNUM + h) * SEQ;
    const float4* kb = (const float4*)(k + bh * HD);
    const float4* vb = (const float4*)(v + bh * HD);

    // load this lane's 8 q dims
    const float4* qp = (const float4*)(q + (bh + (size_t)n) * HD) + ln8 * 2;
    const float4 qa = qp[0];
    const float4 qb = qp[1];
    const float sc = 0.125f;   // 1/sqrt(64)

    // ---- pass 1: scores, fused q.(k+se), 3-shfl octet reduce ----
    float s[NOFF];
    #pragma unroll
    for (int i = 0; i < NOFF; i++) {
        const int d = c_off[i];
        const int row = (n >= d) ? (n - d) : 0;   // clamped (masked later)
        const float4* kr = kb + (size_t)row * 16 + ln8 * 2;
        float4 k0 = kr[0];
        float4 k1 = kr[1];
        float4 e0 = s_se[i * 16 + ln8 * 2];
        float4 e1 = s_se[i * 16 + ln8 * 2 + 1];
        float p0 = qa.x * (k0.x + e0.x);
        float p1 = qa.y * (k0.y + e0.y);
        p0 = fmaf(qa.z, k0.z + e0.z, p0);
        p1 = fmaf(qa.w, k0.w + e0.w, p1);
        p0 = fmaf(qb.x, k1.x + e1.x, p0);
        p1 = fmaf(qb.y, k1.y + e1.y, p1);
        p0 = fmaf(qb.z, k1.z + e1.z, p0);
        p1 = fmaf(qb.w, k1.w + e1.w, p1);
        float part = p0 + p1;
        part += __shfl_xor_sync(0xffffffffu, part, 4);
        part += __shfl_xor_sync(0xffffffffu, part, 2);
        part += __shfl_xor_sync(0xffffffffu, part, 1);
        s[i] = (n >= d) ? fmaf(part, sc, s_pb[i]) : -1e30f;
    }

    // ---- softmax over 44 offsets (lanes of an octet hold identical copies) ----
    float m = -FLT_MAX;
    #pragma unroll
    for (int i = 0; i < NOFF; i++) m = fmaxf(m, s[i]);
    float sum = 0.f;
    #pragma unroll
    for (int i = 0; i < NOFF; i++) {
        float e = __expf(s[i] - m);
        s[i] = e;
        sum += e;
    }
    const float inv = 1.0f / sum;

    // ---- pass 2: rotated-V accumulation ----
    float4 oa = make_float4(0.f, 0.f, 0.f, 0.f);
    float4 ob = make_float4(0.f, 0.f, 0.f, 0.f);
    #pragma unroll
    for (int i = 0; i < NOFF; i++) {
        const int d = c_off[i];
        const int row = (n >= d) ? (n - d) : 0;
        const float w  = (n >= d) ? s[i] * inv : 0.f;
        const float pc = w * s_cos[i];
        const float ps = w * s_sin[i];
        const float4* vr = vb + (size_t)row * 16 + ln8 * 2;
        float4 v0 = vr[0];
        float4 v1 = vr[1];
        oa.x = fmaf(v0.x, pc, fmaf(-v0.y, ps, oa.x));
        oa.y = fmaf(v0.x, ps, fmaf( v0.y, pc, oa.y));
        oa.z = fmaf(v0.z, pc, fmaf(-v0.w, ps, oa.z));
        oa.w = fmaf(v0.z, ps, fmaf( v0.w, pc, oa.w));
        ob.x = fmaf(v1.x, pc, fmaf(-v1.y, ps, ob.x));
        ob.y = fmaf(v1.x, ps, fmaf( v1.y, pc, ob.y));
        ob.z = fmaf(v1.z, pc, fmaf(-v1.w, ps, ob.z));
        ob.w = fmaf(v1.z, ps, fmaf( v1.w, pc, ob.w));
    }

    // ---- store ----
    float4* op = (float4*)(out + (bh + (size_t)n) * HD) + ln8 * 2;
    op[0] = oa;
    op[1] = ob;
}

extern "C" void kernel_launch(void* const* d_in, const int* in_sizes, int n_in,
                              void* d_out, int out_size) {
    const float* q  = (const float*)d_in[0];
    const float* k  = (const float*)d_in[1];
    const float* v  = (const float*)d_in[2];
    const float* pb = (const float*)d_in[3];
    const float* se = (const float*)d_in[4];
    const float* ph = (const float*)d_in[5];
    float* out = (float*)d_out;

    dim3 grid(SEQ / QPB, HNUM, BNUM);
    dsqg_attn_kernel<<<grid, TPB>>>(q, k, v, pb, se, ph, out);
}

// round 4
// speedup vs baseline: 4.4700x; 3.4360x over previous
#include <cuda_runtime.h>
#include <float.h>

#define NOFF    44
#define NDENSE  33
#define NSPARSE 11
#define HD      64
#define SEQ     8192
#define HNUM    16
#define BNUM    2
#define TPB     128
#define NWARP   (TPB / 32)
#define QPW     8                 // queries per warp (4 octets x 2)
#define QPB     (NWARP * QPW)     // 32 queries per block

__constant__ int c_soff[NSPARSE] = {48,64,96,128,192,256,384,512,768,1024,1536};

__device__ __forceinline__ float4 f4add(float4 a, float4 b) {
    return make_float4(a.x + b.x, a.y + b.y, a.z + b.z, a.w + b.w);
}

__device__ __forceinline__ float dot8(float4 a0, float4 a1, float4 b0, float4 b1) {
    float x = a0.x * b0.x;
    float y = a0.y * b0.y;
    x = fmaf(a0.z, b0.z, x);  y = fmaf(a0.w, b0.w, y);
    x = fmaf(a1.x, b1.x, x);  y = fmaf(a1.y, b1.y, y);
    x = fmaf(a1.z, b1.z, x);  y = fmaf(a1.w, b1.w, y);
    return x + y;
}

__device__ __forceinline__ float red8(float p) {
    p += __shfl_xor_sync(0xffffffffu, p, 1);
    p += __shfl_xor_sync(0xffffffffu, p, 2);
    p += __shfl_xor_sync(0xffffffffu, p, 4);
    return p;
}

__device__ __forceinline__ void rotacc(float4& acc, float4 vv, float pc, float ps) {
    acc.x = fmaf(vv.x, pc, fmaf(-vv.y, ps, acc.x));
    acc.y = fmaf(vv.x, ps, fmaf( vv.y, pc, acc.y));
    acc.z = fmaf(vv.z, pc, fmaf(-vv.w, ps, acc.z));
    acc.w = fmaf(vv.z, ps, fmaf( vv.w, pc, acc.w));
}

__global__ __launch_bounds__(TPB, 4)
void dsqg_attn_kernel(const float* __restrict__ q,
                      const float* __restrict__ k,
                      const float* __restrict__ v,
                      const float* __restrict__ pb,
                      const float* __restrict__ se,
                      const float* __restrict__ ph,
                      float* __restrict__ out) {
    const int lane = threadIdx.x & 31;
    const int wid  = threadIdx.x >> 5;
    const int o    = lane >> 3;      // octet id (0..3)
    const int ln8  = lane & 7;       // lane within octet

    __shared__ float4 s_se[NOFF * 16];
    __shared__ float  s_pb[NOFF];
    __shared__ float  s_cos[NOFF];
    __shared__ float  s_sin[NOFF];
    __shared__ float  s_p[QPB][NOFF];

    for (int i = threadIdx.x; i < NOFF * 16; i += TPB)
        s_se[i] = ((const float4*)se)[i];
    if (threadIdx.x < NOFF) {
        const int h0 = blockIdx.y;
        s_pb[threadIdx.x] = pb[threadIdx.x * HNUM + h0];
        float p = ph[threadIdx.x * HNUM + h0];
        s_cos[threadIdx.x] = cosf(p);
        s_sin[threadIdx.x] = sinf(p);
    }
    __syncthreads();

    const int h = blockIdx.y;
    const int b = blockIdx.z;
    const size_t bh = ((size_t)b * HNUM + h) * SEQ;
    const float4* kb = (const float4*)(k + bh * HD);
    const float4* vb = (const float4*)(v + bh * HD);

    const int q1  = blockIdx.x * QPB + wid * QPW + 2 * o;
    const int q2  = q1 + 1;
    const int ql1 = wid * QPW + 2 * o;

    // q registers: split-row layout (float4 slots ln8 and 8+ln8)
    const float4* q1p = (const float4*)(q + (bh + (size_t)q1) * HD);
    const float4* q2p = q1p + 16;
    const float4 q1a = q1p[ln8],     q1b = q1p[8 + ln8];
    const float4 q2a = q2p[ln8],     q2b = q2p[8 + ln8];

    const float sc = 0.125f;   // 1/sqrt(64)

    // ================= pass 1: dense scores (pipelined pair) =================
    {
        float4 cur0 = kb[(size_t)q2 * 16 + ln8];
        float4 cur1 = kb[(size_t)q2 * 16 + 8 + ln8];
        #pragma unroll 4
        for (int d = 0; d < NDENSE; d++) {
            float4 e0 = s_se[d * 16 + ln8];
            float4 e1 = s_se[d * 16 + 8 + ln8];
            float p2 = dot8(q2a, q2b, f4add(cur0, e0), f4add(cur1, e1));
            int rn = q2 - d - 1;
            int rc = rn < 0 ? 0 : rn;
            float4 n0 = kb[(size_t)rc * 16 + ln8];
            float4 n1 = kb[(size_t)rc * 16 + 8 + ln8];
            float p1 = dot8(q1a, q1b, f4add(n0, e0), f4add(n1, e1));
            p2 = red8(p2);
            p1 = red8(p1);
            if (ln8 == 0) {
                s_p[ql1 + 1][d] = (q2 >= d) ? fmaf(p2, sc, s_pb[d]) : -1e30f;
                s_p[ql1][d]     = (q1 >= d) ? fmaf(p1, sc, s_pb[d]) : -1e30f;
            }
            cur0 = n0; cur1 = n1;
        }
    }

    // ================= pass 1: sparse scores =================
    #pragma unroll
    for (int i = 0; i < NSPARSE; i++) {
        const int d  = c_soff[i];
        const int io = NDENSE + i;
        float4 e0 = s_se[io * 16 + ln8];
        float4 e1 = s_se[io * 16 + 8 + ln8];
        int r2 = q2 - d, r1 = q1 - d;
        int rc2 = r2 < 0 ? 0 : r2;
        int rc1 = r1 < 0 ? 0 : r1;
        float4 k20 = kb[(size_t)rc2 * 16 + ln8];
        float4 k21 = kb[(size_t)rc2 * 16 + 8 + ln8];
        float4 k10 = kb[(size_t)rc1 * 16 + ln8];
        float4 k11 = kb[(size_t)rc1 * 16 + 8 + ln8];
        float p2 = dot8(q2a, q2b, f4add(k20, e0), f4add(k21, e1));
        float p1 = dot8(q1a, q1b, f4add(k10, e0), f4add(k11, e1));
        p2 = red8(p2);
        p1 = red8(p1);
        if (ln8 == 0) {
            s_p[ql1 + 1][io] = (r2 >= 0) ? fmaf(p2, sc, s_pb[io]) : -1e30f;
            s_p[ql1][io]     = (r1 >= 0) ? fmaf(p1, sc, s_pb[io]) : -1e30f;
        }
    }
    __syncwarp();

    // ================= softmax (4 lanes per query, 11 offsets each) =================
    {
        const int qsel = ql1 + ((ln8 >> 2) & 1);   // lanes 0-3 -> q1, 4-7 -> q2
        const int j    = ln8 & 3;
        float vals[11];
        float vmax = -FLT_MAX;
        #pragma unroll
        for (int t = 0; t < 11; t++) {
            vals[t] = s_p[qsel][j * 11 + t];
            vmax = fmaxf(vmax, vals[t]);
        }
        vmax = fmaxf(vmax, __shfl_xor_sync(0xffffffffu, vmax, 1));
        vmax = fmaxf(vmax, __shfl_xor_sync(0xffffffffu, vmax, 2));
        float sum = 0.f;
        #pragma unroll
        for (int t = 0; t < 11; t++) {
            vals[t] = __expf(vals[t] - vmax);
            sum += vals[t];
        }
        sum += __shfl_xor_sync(0xffffffffu, sum, 1);
        sum += __shfl_xor_sync(0xffffffffu, sum, 2);
        const float inv = 1.0f / sum;
        #pragma unroll
        for (int t = 0; t < 11; t++)
            s_p[qsel][j * 11 + t] = vals[t] * inv;
    }
    __syncwarp();

    // ================= pass 2: rotated-V accumulation =================
    float4 a1a = make_float4(0.f, 0.f, 0.f, 0.f);
    float4 a1b = make_float4(0.f, 0.f, 0.f, 0.f);
    float4 a2a = make_float4(0.f, 0.f, 0.f, 0.f);
    float4 a2b = make_float4(0.f, 0.f, 0.f, 0.f);

    // dense (pipelined pair; masked offsets have p == 0)
    {
        float4 cur0 = vb[(size_t)q2 * 16 + ln8];
        float4 cur1 = vb[(size_t)q2 * 16 + 8 + ln8];
        #pragma unroll 4
        for (int d = 0; d < NDENSE; d++) {
            float p2 = s_p[ql1 + 1][d];
            float p1 = s_p[ql1][d];
            float cc = s_cos[d], ss = s_sin[d];
            float pc2 = p2 * cc, ps2 = p2 * ss;
            float pc1 = p1 * cc, ps1 = p1 * ss;
            rotacc(a2a, cur0, pc2, ps2);
            rotacc(a2b, cur1, pc2, ps2);
            int rn = q2 - d - 1;
            int rc = rn < 0 ? 0 : rn;
            float4 n0 = vb[(size_t)rc * 16 + ln8];
            float4 n1 = vb[(size_t)rc * 16 + 8 + ln8];
            rotacc(a1a, n0, pc1, ps1);
            rotacc(a1b, n1, pc1, ps1);
            cur0 = n0; cur1 = n1;
        }
    }

    // sparse
    #pragma unroll
    for (int i = 0; i < NSPARSE; i++) {
        const int d  = c_soff[i];
        const int io = NDENSE + i;
        float p2 = s_p[ql1 + 1][io];
        float p1 = s_p[ql1][io];
        float cc = s_cos[io], ss = s_sin[io];
        float pc2 = p2 * cc, ps2 = p2 * ss;
        float pc1 = p1 * cc, ps1 = p1 * ss;
        int r2 = q2 - d, r1 = q1 - d;
        int rc2 = r2 < 0 ? 0 : r2;
        int rc1 = r1 < 0 ? 0 : r1;
        float4 v20 = vb[(size_t)rc2 * 16 + ln8];
        float4 v21 = vb[(size_t)rc2 * 16 + 8 + ln8];
        float4 v10 = vb[(size_t)rc1 * 16 + ln8];
        float4 v11 = vb[(size_t)rc1 * 16 + 8 + ln8];
        rotacc(a2a, v20, pc2, ps2);
        rotacc(a2b, v21, pc2, ps2);
        rotacc(a1a, v10, pc1, ps1);
        rotacc(a1b, v11, pc1, ps1);
    }

    // ================= store =================
    float4* o1 = (float4*)(out + (bh + (size_t)q1) * HD);
    float4* o2 = o1 + 16;
    o1[ln8]     = a1a;
    o1[8 + ln8] = a1b;
    o2[ln8]     = a2a;
    o2[8 + ln8] = a2b;
}

extern "C" void kernel_launch(void* const* d_in, const int* in_sizes, int n_in,
                              void* d_out, int out_size) {
    const float* q  = (const float*)d_in[0];
    const float* k  = (const float*)d_in[1];
    const float* v  = (const float*)d_in[2];
    const float* pb = (const float*)d_in[3];
    const float* se = (const float*)d_in[4];
    const float* ph = (const float*)d_in[5];
    float* out = (float*)d_out;

    dim3 grid(SEQ / QPB, HNUM, BNUM);
    dsqg_attn_kernel<<<grid, TPB>>>(q, k, v, pb, se, ph, out);
}

// round 5
// speedup vs baseline: 5.8560x; 1.3101x over previous
#include <cuda_runtime.h>
#include <float.h>

#define NOFF    44
#define NDENSE  33
#define NSPARSE 11
#define HD      64
#define SEQ     8192
#define HNUM    16
#define BNUM    2
#define TPB     128
#define NWARP   (TPB / 32)
#define QT      4                  // queries per octet (register FIFO depth)
#define QPW     (4 * QT)           // 16 queries per warp
#define QPB     (NWARP * QPW)      // 64 queries per block
#define SPAD    45                 // padded score row (kills bank conflicts)

__constant__ int c_soff[NSPARSE] = {48,64,96,128,192,256,384,512,768,1024,1536};

__device__ __forceinline__ float4 f4add(float4 a, float4 b) {
    return make_float4(a.x + b.x, a.y + b.y, a.z + b.z, a.w + b.w);
}

__device__ __forceinline__ float dot8(float4 a0, float4 a1, float4 b0, float4 b1) {
    float x = a0.x * b0.x;
    float y = a0.y * b0.y;
    x = fmaf(a0.z, b0.z, x);  y = fmaf(a0.w, b0.w, y);
    x = fmaf(a1.x, b1.x, x);  y = fmaf(a1.y, b1.y, y);
    x = fmaf(a1.z, b1.z, x);  y = fmaf(a1.w, b1.w, y);
    return x + y;
}

__device__ __forceinline__ float red8(float p) {
    p += __shfl_xor_sync(0xffffffffu, p, 1);
    p += __shfl_xor_sync(0xffffffffu, p, 2);
    p += __shfl_xor_sync(0xffffffffu, p, 4);
    return p;
}

__device__ __forceinline__ void rotacc(float4& acc, float4 vv, float pc, float ps) {
    acc.x = fmaf(vv.x, pc, fmaf(-vv.y, ps, acc.x));
    acc.y = fmaf(vv.x, ps, fmaf( vv.y, pc, acc.y));
    acc.z = fmaf(vv.z, pc, fmaf(-vv.w, ps, acc.z));
    acc.w = fmaf(vv.z, ps, fmaf( vv.w, pc, acc.w));
}

__global__ __launch_bounds__(TPB, 4)
void dsqg_attn_kernel(const float* __restrict__ q,
                      const float* __restrict__ k,
                      const float* __restrict__ v,
                      const float* __restrict__ pb,
                      const float* __restrict__ se,
                      const float* __restrict__ ph,
                      float* __restrict__ out) {
    const int lane = threadIdx.x & 31;
    const int wid  = threadIdx.x >> 5;
    const int o    = lane >> 3;      // octet id (0..3)
    const int ln8  = lane & 7;       // lane within octet

    __shared__ float4 s_se[NOFF * 16];
    __shared__ float  s_pb[NOFF];
    __shared__ float  s_cos[NOFF];
    __shared__ float  s_sin[NOFF];
    __shared__ float  s_p[QPB][SPAD];

    for (int i = threadIdx.x; i < NOFF * 16; i += TPB)
        s_se[i] = ((const float4*)se)[i];
    if (threadIdx.x < NOFF) {
        const int h0 = blockIdx.y;
        s_pb[threadIdx.x] = pb[threadIdx.x * HNUM + h0];
        float p = ph[threadIdx.x * HNUM + h0];
        s_cos[threadIdx.x] = cosf(p);
        s_sin[threadIdx.x] = sinf(p);
    }
    __syncthreads();

    const int h = blockIdx.y;
    const int b = blockIdx.z;
    const size_t bh = ((size_t)b * HNUM + h) * SEQ;
    const float4* kb = (const float4*)(k + bh * HD);
    const float4* vb = (const float4*)(v + bh * HD);

    // this octet's QT queries: n0..n0+3; local score rows ql0..ql0+3
    const int ql0 = wid * QPW + o * QT;
    const int n0  = blockIdx.x * QPB + ql0;
    const int n3  = n0 + 3;

    // q registers, split-row layout: slot idx t = query n0+t
    float4 qa[QT], qb[QT];
    #pragma unroll
    for (int t = 0; t < QT; t++) {
        const float4* qp = (const float4*)(q + (bh + (size_t)(n0 + t)) * HD);
        qa[t] = qp[ln8];
        qb[t] = qp[8 + ln8];
    }

    const float sc = 0.125f;   // 1/sqrt(64)

    // ================= pass 1: dense scores (4-deep row FIFO) =================
    {
        // f[j] holds row (n3 - d - j); prologue d=0: rows n3, n2, n1, n0
        float4 f0[4], f1[4];
        #pragma unroll
        for (int j = 0; j < 4; j++) {
            const float4* kr = kb + (size_t)(n3 - j) * 16;
            f0[j] = kr[ln8];
            f1[j] = kr[8 + ln8];
        }
        #pragma unroll 3
        for (int d = 0; d < NDENSE; d++) {
            float4 e0 = s_se[d * 16 + ln8];
            float4 e1 = s_se[d * 16 + 8 + ln8];
            float p3 = dot8(qa[3], qb[3], f4add(f0[0], e0), f4add(f1[0], e1));
            float p2 = dot8(qa[2], qb[2], f4add(f0[1], e0), f4add(f1[1], e1));
            float p1 = dot8(qa[1], qb[1], f4add(f0[2], e0), f4add(f1[2], e1));
            float p0 = dot8(qa[0], qb[0], f4add(f0[3], e0), f4add(f1[3], e1));
            // slide window: new bottom row = n0 - d - 1
            int rn = n0 - d - 1;
            int rc = rn < 0 ? 0 : rn;
            f0[0] = f0[1]; f1[0] = f1[1];
            f0[1] = f0[2]; f1[1] = f1[2];
            f0[2] = f0[3]; f1[2] = f1[3];
            {
                const float4* kr = kb + (size_t)rc * 16;
                f0[3] = kr[ln8];
                f1[3] = kr[8 + ln8];
            }
            p3 = red8(p3); p2 = red8(p2); p1 = red8(p1); p0 = red8(p0);
            if (ln8 == 0) {
                float bias = s_pb[d];
                s_p[ql0 + 3][d] = (n3     >= d) ? fmaf(p3, sc, bias) : -1e30f;
                s_p[ql0 + 2][d] = (n0 + 2 >= d) ? fmaf(p2, sc, bias) : -1e30f;
                s_p[ql0 + 1][d] = (n0 + 1 >= d) ? fmaf(p1, sc, bias) : -1e30f;
                s_p[ql0    ][d] = (n0     >= d) ? fmaf(p0, sc, bias) : -1e30f;
            }
        }
    }

    // ================= pass 1: sparse scores =================
    #pragma unroll
    for (int i = 0; i < NSPARSE; i++) {
        const int d  = c_soff[i];
        const int io = NDENSE + i;
        float4 e0 = s_se[io * 16 + ln8];
        float4 e1 = s_se[io * 16 + 8 + ln8];
        float ps_[QT];
        #pragma unroll
        for (int t = 0; t < QT; t++) {
            int r  = n0 + t - d;
            int rc = r < 0 ? 0 : r;
            const float4* kr = kb + (size_t)rc * 16;
            ps_[t] = dot8(qa[t], qb[t], f4add(kr[ln8], e0), f4add(kr[8 + ln8], e1));
        }
        #pragma unroll
        for (int t = 0; t < QT; t++) ps_[t] = red8(ps_[t]);
        if (ln8 == 0) {
            float bias = s_pb[io];
            #pragma unroll
            for (int t = 0; t < QT; t++)
                s_p[ql0 + t][io] = (n0 + t >= d) ? fmaf(ps_[t], sc, bias) : -1e30f;
        }
    }
    __syncwarp();

    // ====== softmax: 2 lanes per query, 22 offsets each ======
    {
        const int qloc = wid * QPW + (lane & 15);
        const int half = lane >> 4;             // 0 or 1
        const int base = half * 22;
        float vals[22];
        float vmax = -FLT_MAX;
        #pragma unroll
        for (int t = 0; t < 22; t++) {
            vals[t] = s_p[qloc][base + t];
            vmax = fmaxf(vmax, vals[t]);
        }
        vmax = fmaxf(vmax, __shfl_xor_sync(0xffffffffu, vmax, 16));
        float sum = 0.f;
        #pragma unroll
        for (int t = 0; t < 22; t++) {
            vals[t] = __expf(vals[t] - vmax);
            sum += vals[t];
        }
        sum += __shfl_xor_sync(0xffffffffu, sum, 16);
        const float inv = 1.0f / sum;
        #pragma unroll
        for (int t = 0; t < 22; t++)
            s_p[qloc][base + t] = vals[t] * inv;
    }
    __syncwarp();

    // ================= pass 2: rotated-V accumulation =================
    float4 aa[QT], ab[QT];
    #pragma unroll
    for (int t = 0; t < QT; t++) {
        aa[t] = make_float4(0.f, 0.f, 0.f, 0.f);
        ab[t] = make_float4(0.f, 0.f, 0.f, 0.f);
    }

    // dense (4-deep FIFO; masked offsets have p == 0)
    {
        float4 f0[4], f1[4];
        #pragma unroll
        for (int j = 0; j < 4; j++) {
            const float4* vr = vb + (size_t)(n3 - j) * 16;
            f0[j] = vr[ln8];
            f1[j] = vr[8 + ln8];
        }
        #pragma unroll 3
        for (int d = 0; d < NDENSE; d++) {
            float cc = s_cos[d], ss = s_sin[d];
            #pragma unroll
            for (int t = 0; t < QT; t++) {
                float w  = s_p[ql0 + t][d];
                float pc = w * cc, ps = w * ss;
                rotacc(aa[t], f0[3 - t], pc, ps);
                rotacc(ab[t], f1[3 - t], pc, ps);
            }
            int rn = n0 - d - 1;
            int rc = rn < 0 ? 0 : rn;
            f0[0] = f0[1]; f1[0] = f1[1];
            f0[1] = f0[2]; f1[1] = f1[2];
            f0[2] = f0[3]; f1[2] = f1[3];
            {
                const float4* vr = vb + (size_t)rc * 16;
                f0[3] = vr[ln8];
                f1[3] = vr[8 + ln8];
            }
        }
    }

    // sparse
    #pragma unroll
    for (int i = 0; i < NSPARSE; i++) {
        const int d  = c_soff[i];
        const int io = NDENSE + i;
        float cc = s_cos[io], ss = s_sin[io];
        #pragma unroll
        for (int t = 0; t < QT; t++) {
            int r  = n0 + t - d;
            int rc = r < 0 ? 0 : r;
            float w  = s_p[ql0 + t][io];
            float pc = w * cc, ps = w * ss;
            const float4* vr = vb + (size_t)rc * 16;
            rotacc(aa[t], vr[ln8],     pc, ps);
            rotacc(ab[t], vr[8 + ln8], pc, ps);
        }
    }

    // ================= store =================
    #pragma unroll
    for (int t = 0; t < QT; t++) {
        float4* op = (float4*)(out + (bh + (size_t)(n0 + t)) * HD);
        op[ln8]     = aa[t];
        op[8 + ln8] = ab[t];
    }
}

extern "C" void kernel_launch(void* const* d_in, const int* in_sizes, int n_in,
                              void* d_out, int out_size) {
    const float* q  = (const float*)d_in[0];
    const float* k  = (const float*)d_in[1];
    const float* v  = (const float*)d_in[2];
    const float* pb = (const float*)d_in[3];
    const float* se = (const float*)d_in[4];
    const float* ph = (const float*)d_in[5];
    float* out = (float*)d_out;

    dim3 grid(SEQ / QPB, HNUM, BNUM);
    dsqg_attn_kernel<<<grid, TPB>>>(q, k, v, pb, se, ph, out);
}

// round 6
// speedup vs baseline: 6.4407x; 1.0999x over previous
#include <cuda_runtime.h>
#include <float.h>

#define NOFF    44
#define NDENSE  33
#define NSPARSE 11
#define HD      64
#define SEQ     8192
#define HNUM    16
#define BNUM    2
#define TPB     128
#define NWARP   (TPB / 32)
#define QT      4                  // queries per octet (register FIFO depth)
#define QPW     (4 * QT)           // 16 queries per warp
#define QPB     (NWARP * QPW)      // 64 queries per block
#define SPAD    45                 // padded score row (kills bank conflicts)

typedef unsigned long long ull;

__constant__ int c_soff[NSPARSE] = {48,64,96,128,192,256,384,512,768,1024,1536};

// ---- packed f32x2 helpers (Blackwell FFMA2 path, PTX-only) ----
__device__ __forceinline__ ull f2fma(ull a, ull b, ull c) {
    ull d; asm("fma.rn.f32x2 %0, %1, %2, %3;" : "=l"(d) : "l"(a), "l"(b), "l"(c)); return d;
}
__device__ __forceinline__ ull f2add(ull a, ull b) {
    ull d; asm("add.rn.f32x2 %0, %1, %2;" : "=l"(d) : "l"(a), "l"(b)); return d;
}
__device__ __forceinline__ ull f2mul(ull a, ull b) {
    ull d; asm("mul.rn.f32x2 %0, %1, %2;" : "=l"(d) : "l"(a), "l"(b)); return d;
}
__device__ __forceinline__ ull f2pack(float lo, float hi) {
    ull d; asm("mov.b64 %0, {%1, %2};" : "=l"(d) : "f"(lo), "f"(hi)); return d;
}
__device__ __forceinline__ float2 f2unpack(ull v) {
    float lo, hi; asm("mov.b64 {%0, %1}, %2;" : "=f"(lo), "=f"(hi) : "l"(v));
    return make_float2(lo, hi);
}

// packed dot over 8 floats: q (2x ulonglong2) . b (2x ulonglong2)
__device__ __forceinline__ float dot8p(ulonglong2 qa, ulonglong2 qb,
                                       ulonglong2 b0, ulonglong2 b1) {
    ull acc = f2mul(qa.x, b0.x);
    acc = f2fma(qa.y, b0.y, acc);
    acc = f2fma(qb.x, b1.x, acc);
    acc = f2fma(qb.y, b1.y, acc);
    float2 r = f2unpack(acc);
    return r.x + r.y;
}

__device__ __forceinline__ ulonglong2 u2add(ulonglong2 a, ulonglong2 b) {
    ulonglong2 r; r.x = f2add(a.x, b.x); r.y = f2add(a.y, b.y); return r;
}

__device__ __forceinline__ float red8(float p) {
    p += __shfl_xor_sync(0xffffffffu, p, 1);
    p += __shfl_xor_sync(0xffffffffu, p, 2);
    p += __shfl_xor_sync(0xffffffffu, p, 4);
    return p;
}

__global__ __launch_bounds__(TPB, 4)
void dsqg_attn_kernel(const float* __restrict__ q,
                      const float* __restrict__ k,
                      const float* __restrict__ v,
                      const float* __restrict__ pb,
                      const float* __restrict__ se,
                      const float* __restrict__ ph,
                      float* __restrict__ out) {
    const int lane = threadIdx.x & 31;
    const int wid  = threadIdx.x >> 5;
    const int o    = lane >> 3;      // octet id (0..3)
    const int ln8  = lane & 7;       // lane within octet

    __shared__ ulonglong2 s_se[NOFF * 16];
    __shared__ float  s_pb[NOFF];
    __shared__ float  s_cos[NOFF];
    __shared__ float  s_sin[NOFF];
    __shared__ float  s_p[QPB][SPAD];

    for (int i = threadIdx.x; i < NOFF * 16; i += TPB)
        s_se[i] = ((const ulonglong2*)se)[i];
    if (threadIdx.x < NOFF) {
        const int h0 = blockIdx.y;
        s_pb[threadIdx.x] = pb[threadIdx.x * HNUM + h0];
        float p = ph[threadIdx.x * HNUM + h0];
        s_cos[threadIdx.x] = cosf(p);
        s_sin[threadIdx.x] = sinf(p);
    }
    __syncthreads();

    const int h = blockIdx.y;
    const int b = blockIdx.z;
    const size_t bh = ((size_t)b * HNUM + h) * SEQ;
    const ulonglong2* kb = (const ulonglong2*)(k + bh * HD);
    const ulonglong2* vb = (const ulonglong2*)(v + bh * HD);

    const int ql0 = wid * QPW + o * QT;
    const int n0  = blockIdx.x * QPB + ql0;
    const int n3  = n0 + 3;

    // q registers, split-row layout
    ulonglong2 qa[QT], qbr[QT];
    #pragma unroll
    for (int t = 0; t < QT; t++) {
        const ulonglong2* qp = (const ulonglong2*)(q + (bh + (size_t)(n0 + t)) * HD);
        qa[t]  = qp[ln8];
        qbr[t] = qp[8 + ln8];
    }

    const float sc = 0.125f;   // 1/sqrt(64)

    // ================= pass 1: dense scores (4-deep row FIFO, packed) =================
    {
        ulonglong2 f0[4], f1[4];
        #pragma unroll
        for (int j = 0; j < 4; j++) {
            const ulonglong2* kr = kb + (size_t)(n3 - j) * 16;
            f0[j] = kr[ln8];
            f1[j] = kr[8 + ln8];
        }
        #pragma unroll 3
        for (int d = 0; d < NDENSE; d++) {
            ulonglong2 e0 = s_se[d * 16 + ln8];
            ulonglong2 e1 = s_se[d * 16 + 8 + ln8];
            float p3 = dot8p(qa[3], qbr[3], u2add(f0[0], e0), u2add(f1[0], e1));
            float p2 = dot8p(qa[2], qbr[2], u2add(f0[1], e0), u2add(f1[1], e1));
            float p1 = dot8p(qa[1], qbr[1], u2add(f0[2], e0), u2add(f1[2], e1));
            float p0 = dot8p(qa[0], qbr[0], u2add(f0[3], e0), u2add(f1[3], e1));
            int rn = n0 - d - 1;
            int rc = rn < 0 ? 0 : rn;
            f0[0] = f0[1]; f1[0] = f1[1];
            f0[1] = f0[2]; f1[1] = f1[2];
            f0[2] = f0[3]; f1[2] = f1[3];
            {
                const ulonglong2* kr = kb + (size_t)rc * 16;
                f0[3] = kr[ln8];
                f1[3] = kr[8 + ln8];
            }
            p3 = red8(p3); p2 = red8(p2); p1 = red8(p1); p0 = red8(p0);
            if (ln8 == 0) {
                float bias = s_pb[d];
                s_p[ql0 + 3][d] = (n3     >= d) ? fmaf(p3, sc, bias) : -1e30f;
                s_p[ql0 + 2][d] = (n0 + 2 >= d) ? fmaf(p2, sc, bias) : -1e30f;
                s_p[ql0 + 1][d] = (n0 + 1 >= d) ? fmaf(p1, sc, bias) : -1e30f;
                s_p[ql0    ][d] = (n0     >= d) ? fmaf(p0, sc, bias) : -1e30f;
            }
        }
    }

    // ================= pass 1: sparse scores (packed) =================
    #pragma unroll
    for (int i = 0; i < NSPARSE; i++) {
        const int d  = c_soff[i];
        const int io = NDENSE + i;
        ulonglong2 e0 = s_se[io * 16 + ln8];
        ulonglong2 e1 = s_se[io * 16 + 8 + ln8];
        float ps_[QT];
        #pragma unroll
        for (int t = 0; t < QT; t++) {
            int r  = n0 + t - d;
            int rc = r < 0 ? 0 : r;
            const ulonglong2* kr = kb + (size_t)rc * 16;
            ps_[t] = dot8p(qa[t], qbr[t], u2add(kr[ln8], e0), u2add(kr[8 + ln8], e1));
        }
        #pragma unroll
        for (int t = 0; t < QT; t++) ps_[t] = red8(ps_[t]);
        if (ln8 == 0) {
            float bias = s_pb[io];
            #pragma unroll
            for (int t = 0; t < QT; t++)
                s_p[ql0 + t][io] = (n0 + t >= d) ? fmaf(ps_[t], sc, bias) : -1e30f;
        }
    }
    __syncwarp();

    // ====== softmax: 2 lanes per query, 22 offsets each ======
    {
        const int qloc = wid * QPW + (lane & 15);
        const int half = lane >> 4;
        const int base = half * 22;
        float vals[22];
        float vmax = -FLT_MAX;
        #pragma unroll
        for (int t = 0; t < 22; t++) {
            vals[t] = s_p[qloc][base + t];
            vmax = fmaxf(vmax, vals[t]);
        }
        vmax = fmaxf(vmax, __shfl_xor_sync(0xffffffffu, vmax, 16));
        float sum = 0.f;
        #pragma unroll
        for (int t = 0; t < 22; t++) {
            vals[t] = __expf(vals[t] - vmax);
            sum += vals[t];
        }
        sum += __shfl_xor_sync(0xffffffffu, sum, 16);
        const float inv = 1.0f / sum;
        #pragma unroll
        for (int t = 0; t < 22; t++)
            s_p[qloc][base + t] = vals[t] * inv;
    }
    __syncwarp();

    // ========== pass 2: A = sum(w*c*v), B = sum(w*s*v), rotate at the end ==========
    // A/B per query: 4 packed ulls (aA0.x, aA0.y, aA1.x, aA1.y)
    ulonglong2 A0[QT], A1[QT], B0[QT], B1[QT];
    #pragma unroll
    for (int t = 0; t < QT; t++) {
        A0[t].x = A0[t].y = A1[t].x = A1[t].y = 0ull;
        B0[t].x = B0[t].y = B1[t].x = B1[t].y = 0ull;
    }

    // dense (4-deep FIFO; masked offsets have p == 0)
    {
        ulonglong2 f0[4], f1[4];
        #pragma unroll
        for (int j = 0; j < 4; j++) {
            const ulonglong2* vr = vb + (size_t)(n3 - j) * 16;
            f0[j] = vr[ln8];
            f1[j] = vr[8 + ln8];
        }
        #pragma unroll 3
        for (int d = 0; d < NDENSE; d++) {
            float cc = s_cos[d], ss = s_sin[d];
            #pragma unroll
            for (int t = 0; t < QT; t++) {
                float w  = s_p[ql0 + t][d];
                ull pcp = f2pack(w * cc, w * cc);
                ull psp = f2pack(w * ss, w * ss);
                A0[t].x = f2fma(f0[3 - t].x, pcp, A0[t].x);
                A0[t].y = f2fma(f0[3 - t].y, pcp, A0[t].y);
                A1[t].x = f2fma(f1[3 - t].x, pcp, A1[t].x);
                A1[t].y = f2fma(f1[3 - t].y, pcp, A1[t].y);
                B0[t].x = f2fma(f0[3 - t].x, psp, B0[t].x);
                B0[t].y = f2fma(f0[3 - t].y, psp, B0[t].y);
                B1[t].x = f2fma(f1[3 - t].x, psp, B1[t].x);
                B1[t].y = f2fma(f1[3 - t].y, psp, B1[t].y);
            }
            int rn = n0 - d - 1;
            int rc = rn < 0 ? 0 : rn;
            f0[0] = f0[1]; f1[0] = f1[1];
            f0[1] = f0[2]; f1[1] = f1[2];
            f0[2] = f0[3]; f1[2] = f1[3];
            {
                const ulonglong2* vr = vb + (size_t)rc * 16;
                f0[3] = vr[ln8];
                f1[3] = vr[8 + ln8];
            }
        }
    }

    // sparse
    #pragma unroll
    for (int i = 0; i < NSPARSE; i++) {
        const int d  = c_soff[i];
        const int io = NDENSE + i;
        float cc = s_cos[io], ss = s_sin[io];
        #pragma unroll
        for (int t = 0; t < QT; t++) {
            int r  = n0 + t - d;
            int rc = r < 0 ? 0 : r;
            float w  = s_p[ql0 + t][io];
            ull pcp = f2pack(w * cc, w * cc);
            ull psp = f2pack(w * ss, w * ss);
            const ulonglong2* vr = vb + (size_t)rc * 16;
            ulonglong2 v0 = vr[ln8];
            ulonglong2 v1 = vr[8 + ln8];
            A0[t].x = f2fma(v0.x, pcp, A0[t].x);
            A0[t].y = f2fma(v0.y, pcp, A0[t].y);
            A1[t].x = f2fma(v1.x, pcp, A1[t].x);
            A1[t].y = f2fma(v1.y, pcp, A1[t].y);
            B0[t].x = f2fma(v0.x, psp, B0[t].x);
            B0[t].y = f2fma(v0.y, psp, B0[t].y);
            B1[t].x = f2fma(v1.x, psp, B1[t].x);
            B1[t].y = f2fma(v1.y, psp, B1[t].y);
        }
    }

    // ================= final rotation + store =================
    #pragma unroll
    for (int t = 0; t < QT; t++) {
        float4* op = (float4*)(out + (bh + (size_t)(n0 + t)) * HD);
        float2 a0 = f2unpack(A0[t].x), b0 = f2unpack(B0[t].x);
        float2 a1 = f2unpack(A0[t].y), b1 = f2unpack(B0[t].y);
        float2 a2 = f2unpack(A1[t].x), b2 = f2unpack(B1[t].x);
        float2 a3 = f2unpack(A1[t].y), b3 = f2unpack(B1[t].y);
        float4 r0, r1;
        r0.x = a0.x - b0.y;  r0.y = a0.y + b0.x;
        r0.z = a1.x - b1.y;  r0.w = a1.y + b1.x;
        r1.x = a2.x - b2.y;  r1.y = a2.y + b2.x;
        r1.z = a3.x - b3.y;  r1.w = a3.y + b3.x;
        op[ln8]     = r0;
        op[8 + ln8] = r1;
    }
}

extern "C" void kernel_launch(void* const* d_in, const int* in_sizes, int n_in,
                              void* d_out, int out_size) {
    const float* q  = (const float*)d_in[0];
    const float* k  = (const float*)d_in[1];
    const float* v  = (const float*)d_in[2];
    const float* pb = (const float*)d_in[3];
    const float* se = (const float*)d_in[4];
    const float* ph = (const float*)d_in[5];
    float* out = (float*)d_out;

    dim3 grid(SEQ / QPB, HNUM, BNUM);
    dsqg_attn_kernel<<<grid, TPB>>>(q, k, v, pb, se, ph, out);
}